// round 7
// baseline (speedup 1.0000x reference)
#include <cuda_runtime.h>
#include <cuda_fp16.h>
#include <cstdint>

#define BB 16
#define NN 16384
#define CC 128
#define KK 9
#define TM 128
#define THREADS 512
#define NCHUNK_CONV 72          // 8 c8-slices * 9 ko, K=16 each
#define NCHUNK 80               // + 8 skip chunks
#define CHUNK_GB 4096           // W chunk bytes in global
#define ROW_SB 48               // smem row stride: 32B data + 16B pad
#define BUF_B (128 * ROW_SB)    // 6144 per chunk buffer
#define NWBUF 4

// smem layout (bytes)
#define WBUF_OFF 0                          // 4 * 6144 = 24576
#define ABUF_OFF (NWBUF * BUF_B)            // 24576 (+ 2*6144)
#define P2_OFF   (ABUF_OFF + 2 * BUF_B)     // 36864 (+ 128*108*4)
#define IDX_OFF  (P2_OFF + 128 * 108 * 4)   // 92160 (+ 4608)
#define BIAS_OFF (IDX_OFF + 128 * KK * 4)   // 96768 (+ 1024)
#define SMEM_TOTAL (BIAS_OFF + 1024)        // 97792

// W pre-permuted fp16: [chunk][o(128)][p(16)]
__device__ __align__(16) __half g_Wc[NCHUNK_CONV * 2048];
__device__ __align__(16) __half g_Ws[8 * 2048];

// position p -> channel-within-16 (lane's 4 frag k-values = contiguous float4)
__host__ __device__ __forceinline__ int perm16(int p) {
    int e = p & 1;
    return (p < 8) ? ((p >> 1) * 4 + e) : (((p - 8) >> 1) * 4 + 2 + e);
}

__global__ void prep_w(const float* __restrict__ Wc, const float* __restrict__ Ws) {
    int t = blockIdx.x * blockDim.x + threadIdx.x;
    if (t < NCHUNK_CONV * 2048) {
        int qn = t >> 11, r = t & 2047, o = r >> 4, p = r & 15;
        int c8 = qn / 9, ko = qn % 9;
        g_Wc[t] = __float2half_rn(Wc[o * 1152 + ko * CC + c8 * 16 + perm16(p)]);
    }
    if (t < 8 * 2048) {
        int qn = t >> 11, r = t & 2047, o = r >> 4, p = r & 15;
        g_Ws[t] = __float2half_rn(Ws[o * CC + qn * 16 + perm16(p)]);
    }
}

// ---------------- PTX helpers ----------------
__device__ __forceinline__ uint32_t smem_u32(const void* p) {
    uint32_t a;
    asm("{ .reg .u64 t; cvta.to.shared.u64 t, %1; cvt.u32.u64 %0, t; }" : "=r"(a) : "l"(p));
    return a;
}
#define CP_ASYNC16(dst, src) \
    asm volatile("cp.async.cg.shared.global [%0], [%1], 16;" :: "r"(dst), "l"(src))
#define CP_COMMIT() asm volatile("cp.async.commit_group;" ::: "memory")
#define CP_WAIT(n)  asm volatile("cp.async.wait_group %0;" :: "n"(n) : "memory")

__device__ __forceinline__ void ldsm_x4(uint32_t* r, uint32_t addr) {
    asm volatile("ldmatrix.sync.aligned.m8n8.x4.shared.b16 {%0,%1,%2,%3}, [%4];"
                 : "=r"(r[0]), "=r"(r[1]), "=r"(r[2]), "=r"(r[3]) : "r"(addr));
}
__device__ __forceinline__ void mma16816(float* c, const uint32_t* a,
                                         uint32_t b0, uint32_t b1) {
    asm volatile("mma.sync.aligned.m16n8k16.row.col.f32.f16.f16.f32 "
                 "{%0,%1,%2,%3}, {%4,%5,%6,%7}, {%8,%9}, {%0,%1,%2,%3};"
                 : "+f"(c[0]), "+f"(c[1]), "+f"(c[2]), "+f"(c[3])
                 : "r"(a[0]), "r"(a[1]), "r"(a[2]), "r"(a[3]), "r"(b0), "r"(b1));
}
__device__ __forceinline__ float elu(float v) {
    float e;
    asm("ex2.approx.f32 %0, %1;" : "=f"(e) : "f"(v * 1.44269504f));
    return v > 0.f ? v : e - 1.f;
}
__device__ __forceinline__ void fma4(float4& a, float s, const float4& v) {
    a.x = fmaf(s, v.x, a.x); a.y = fmaf(s, v.y, a.y);
    a.z = fmaf(s, v.z, a.z); a.w = fmaf(s, v.w, a.w);
}
__device__ __forceinline__ uint32_t h2pack(float a, float b) {
    __half2 h = __floats2half2_rn(a, b);
    return *reinterpret_cast<uint32_t*>(&h);
}

// chunk fetch: threads 0..255 push 16B each (4KB chunk); everyone commits
__device__ __forceinline__ void issue_chunk(uint32_t wbase, int i, int tid) {
    if (tid < 256) {
        const char* src = (i < NCHUNK_CONV)
            ? (const char*)g_Wc + (size_t)i * CHUNK_GB
            : (const char*)g_Ws + (size_t)(i - NCHUNK_CONV) * CHUNK_GB;
        int o = tid >> 1, h = tid & 1;
        uint32_t dst = wbase + (i & (NWBUF - 1)) * BUF_B + o * ROW_SB + h * 16;
        CP_ASYNC16(dst, src + o * 32 + h * 16);
    }
    CP_COMMIT();
}

__global__ __launch_bounds__(THREADS, 1)
void paiconv_sq(const float* __restrict__ x, const int* __restrict__ idxg,
                const float* __restrict__ P, const float* __restrict__ b_conv,
                const float* __restrict__ b_skip, float* __restrict__ out)
{
    extern __shared__ char smem[];
    const uint32_t sb = smem_u32(smem);
    const int tid  = threadIdx.x;
    const int lane = tid & 31;
    const int wid  = tid >> 5;
    const int n0   = blockIdx.x * TM;
    const int b    = blockIdx.y;

    float* s_P2   = (float*)(smem + P2_OFF);     // [node][ko][12]
    int*   s_idx  = (int*)(smem + IDX_OFF);
    float* s_bias = (float*)(smem + BIAS_OFF);

    issue_chunk(sb + WBUF_OFF, 0, tid);
    issue_chunk(sb + WBUF_OFF, 1, tid);
    issue_chunk(sb + WBUF_OFF, 2, tid);

    for (int t = tid; t < TM * 81; t += THREADS) {
        int node = t / 81, rem = t - node * 81;
        int ko = rem / 9, j = rem - ko * 9;
        s_P2[node * 108 + ko * 12 + j] = P[(size_t)n0 * 81 + t];
    }
    for (int t = tid; t < TM * KK; t += THREADS) s_idx[t] = idxg[n0 * KK + t];
    if (tid < CC)       s_bias[tid] = b_conv[tid];
    else if (tid < 256) s_bias[tid] = b_skip[tid - CC];
    __syncthreads();

    const float* xb = x + (size_t)b * NN * CC;

    // A-producer role: thread owns node row (tid>>2) x 4-channel group (tid&3)
    const int row = tid >> 2;
    const int q4  = (tid & 3) * 16;              // byte offset of float4 in 64B half-slice

    // MMA role: warp grid 4m x 4n, tile m32 x n32
    const int m0 = (wid >> 2) * 32;
    const int nb = (wid & 3) * 32;
    const uint32_t a_l0 = sb + ABUF_OFF + (m0 + (lane & 15)) * ROW_SB + (lane >> 4) * 16;
    const uint32_t b_l0 = sb + WBUF_OFF + (nb + (lane & 15)) * ROW_SB + (lane >> 4) * 16;
    const uint32_t a_st = sb + ABUF_OFF + row * ROW_SB + q4 / 4;  // q*4 bytes

    // neighbor byte offsets for this thread's row
    uint32_t noff[KK];
    #pragma unroll
    for (int j = 0; j < KK; j++) {
        unsigned ix = (unsigned)s_idx[row * KK + j];
        noff[j] = (ix < (unsigned)NN) ? ix * 512u : 0xFFFFFFFFu;
    }

    float acc[32];
    #pragma unroll
    for (int i = 0; i < 32; i++) acc[i] = 0.f;

    int ci = 0;
    for (int c8 = 0; c8 < 8; c8++) {
        // gather row's 9 neighbor float4s for this channel slice (fp32, reused 9x)
        float4 xg[KK];
        #pragma unroll
        for (int j = 0; j < KK; j++) {
            float4 v = make_float4(0.f, 0.f, 0.f, 0.f);
            if (noff[j] != 0xFFFFFFFFu)
                v = __ldg((const float4*)((const char*)xb + (size_t)noff[j] + c8 * 64 + q4));
            xg[j] = v;
        }
        #pragma unroll
        for (int ko = 0; ko < 9; ko++, ci++) {
            // ---- mix (fp32) + ELU -> fp16 A chunk ----
            const float* p = s_P2 + row * 108 + ko * 12;
            float4 pa = *(const float4*)p, pb = *(const float4*)(p + 4);
            float p8 = p[8];
            float4 v = make_float4(0.f, 0.f, 0.f, 0.f);
            fma4(v, pa.x, xg[0]); fma4(v, pa.y, xg[1]);
            fma4(v, pa.z, xg[2]); fma4(v, pa.w, xg[3]);
            fma4(v, pb.x, xg[4]); fma4(v, pb.y, xg[5]);
            fma4(v, pb.z, xg[6]); fma4(v, pb.w, xg[7]);
            fma4(v, p8,   xg[8]);
            uint32_t h0 = h2pack(elu(v.x), elu(v.y));
            uint32_t h1 = h2pack(elu(v.z), elu(v.w));
            uint32_t ad = a_st + (ci & 1) * BUF_B;
            asm volatile("st.shared.b32 [%0], %1;"      :: "r"(ad), "r"(h0) : "memory");
            asm volatile("st.shared.b32 [%0+16], %1;"   :: "r"(ad), "r"(h1) : "memory");

            // ---- pipeline boundary ----
            if (ci < 78) CP_WAIT(2); else if (ci == 78) CP_WAIT(1); else CP_WAIT(0);
            __syncthreads();
            if (ci + 3 < NCHUNK) issue_chunk(sb + WBUF_OFF, ci + 3, tid);

            // ---- MMA: m32 x n32 x k16 ----
            const uint32_t ab = a_l0 + (ci & 1) * BUF_B;
            const uint32_t wb = b_l0 + (ci & 3) * BUF_B;
            uint32_t a0[4], a1[4], bf0[4], bf1[4];
            ldsm_x4(a0, ab);
            ldsm_x4(a1, ab + 16 * ROW_SB);
            ldsm_x4(bf0, wb);
            ldsm_x4(bf1, wb + 16 * ROW_SB);
            mma16816(acc + 0,  a0, bf0[0], bf0[2]);
            mma16816(acc + 4,  a0, bf0[1], bf0[3]);
            mma16816(acc + 8,  a0, bf1[0], bf1[2]);
            mma16816(acc + 12, a0, bf1[1], bf1[3]);
            mma16816(acc + 16, a1, bf0[0], bf0[2]);
            mma16816(acc + 20, a1, bf0[1], bf0[3]);
            mma16816(acc + 24, a1, bf1[0], bf1[2]);
            mma16816(acc + 28, a1, bf1[1], bf1[3]);
        }
    }

    // ---- fold: acc = elu(acc + bc) + bs (register-only) ----
    {
        const int cb = (lane & 3) * 2;
        #pragma unroll
        for (int mi = 0; mi < 2; mi++)
            #pragma unroll
            for (int t = 0; t < 4; t++) {
                int col = nb + t * 8 + cb;
                float2 bc  = *(const float2*)(s_bias + col);
                float2 bs2 = *(const float2*)(s_bias + 128 + col);
                float* a = acc + mi * 16 + t * 4;
                a[0] = elu(a[0] + bc.x) + bs2.x;
                a[1] = elu(a[1] + bc.y) + bs2.y;
                a[2] = elu(a[2] + bc.x) + bs2.x;
                a[3] = elu(a[3] + bc.y) + bs2.y;
            }
    }

    // ---- skip: 8 chunks, A = x (fp16) through same staging ----
    for (int c8 = 0; c8 < 8; c8++, ci++) {
        float4 v = __ldg((const float4*)((const char*)xb + (size_t)(n0 + row) * 512 + c8 * 64 + q4));
        uint32_t h0 = h2pack(v.x, v.y);
        uint32_t h1 = h2pack(v.z, v.w);
        uint32_t ad = a_st + (ci & 1) * BUF_B;
        asm volatile("st.shared.b32 [%0], %1;"    :: "r"(ad), "r"(h0) : "memory");
        asm volatile("st.shared.b32 [%0+16], %1;" :: "r"(ad), "r"(h1) : "memory");

        if (ci < 78) CP_WAIT(2); else if (ci == 78) CP_WAIT(1); else CP_WAIT(0);
        __syncthreads();
        if (ci + 3 < NCHUNK) issue_chunk(sb + WBUF_OFF, ci + 3, tid);

        const uint32_t ab = a_l0 + (ci & 1) * BUF_B;
        const uint32_t wb = b_l0 + (ci & 3) * BUF_B;
        uint32_t a0[4], a1[4], bf0[4], bf1[4];
        ldsm_x4(a0, ab);
        ldsm_x4(a1, ab + 16 * ROW_SB);
        ldsm_x4(bf0, wb);
        ldsm_x4(bf1, wb + 16 * ROW_SB);
        mma16816(acc + 0,  a0, bf0[0], bf0[2]);
        mma16816(acc + 4,  a0, bf0[1], bf0[3]);
        mma16816(acc + 8,  a0, bf1[0], bf1[2]);
        mma16816(acc + 12, a0, bf1[1], bf1[3]);
        mma16816(acc + 16, a1, bf0[0], bf0[2]);
        mma16816(acc + 20, a1, bf0[1], bf0[3]);
        mma16816(acc + 24, a1, bf1[0], bf1[2]);
        mma16816(acc + 28, a1, bf1[1], bf1[3]);
    }

    // ---- epilogue: store ----
    {
        const int cb = (lane & 3) * 2;
        #pragma unroll
        for (int mi = 0; mi < 2; mi++)
            #pragma unroll
            for (int h = 0; h < 2; h++) {
                int r = m0 + mi * 16 + (lane >> 2) + h * 8;
                float* orow = out + ((size_t)b * NN + n0 + r) * CC;
                #pragma unroll
                for (int t = 0; t < 4; t++) {
                    float* a = acc + mi * 16 + t * 4 + h * 2;
                    *(float2*)(orow + nb + t * 8 + cb) = make_float2(a[0], a[1]);
                }
            }
    }
}

extern "C" void kernel_launch(void* const* d_in, const int* in_sizes, int n_in,
                              void* d_out, int out_size) {
    const float* x       = (const float*)d_in[0];
    const int*   indices = (const int*)  d_in[1];
    const float* P       = (const float*)d_in[2];
    const float* W_conv  = (const float*)d_in[3];
    const float* b_conv  = (const float*)d_in[4];
    const float* W_skip  = (const float*)d_in[5];
    const float* b_skip  = (const float*)d_in[6];
    float* out = (float*)d_out;

    prep_w<<<(NCHUNK_CONV * 2048 + 255) / 256, 256>>>(W_conv, W_skip);

    cudaFuncSetAttribute(paiconv_sq,
                         cudaFuncAttributeMaxDynamicSharedMemorySize, SMEM_TOTAL);
    dim3 grid(NN / TM, BB);
    paiconv_sq<<<grid, THREADS, SMEM_TOTAL>>>(x, indices, P, b_conv, b_skip, out);
}